// round 13
// baseline (speedup 1.0000x reference)
#include <cuda_runtime.h>
#include <cuda_bf16.h>
#include <cstdint>

// Problem constants
#define Bb 2048
#define Tt 2048
#define S  16  // SMEM ring steps (4 chunks x 4 steps); buffers padded by S steps
#define C  4   // steps per chunk / commit group
#define NBLK 32   // scan blocks: 2 rows per thread -> 1024 threads
// F=8, U=3, 3U=9

// Scratch: __device__ globals (allocation-free rule). Padded by S steps so
// ALL pipeline loads are unconditional and in-bounds.
__device__ float4 g_bufZ[(size_t)(Tt + S) * Bb];  // {.5*xz0,.5*xz1,.5*xz2, .5*mask}
__device__ float4 g_bufR[(size_t)(Tt + S) * Bb];  // {.5*xr0,.5*xr1,.5*xr2, 0}
__device__ float4 g_bufH[(size_t)(Tt + S) * Bb];  // {xh0, xh1, xh2, 0}
__device__ float  g_outT[(size_t)Tt * Bb];        // out in [t][b] layout

typedef unsigned long long u64;
typedef unsigned int u32;

// HW tanh (sm_75+): 1 MUFU op, rel err ~2^-11
__device__ __forceinline__ float tanh_fast(float x) {
    float y;
    asm("tanh.approx.f32 %0, %1;" : "=f"(y) : "f"(x));
    return y;
}

// f32x2 packed helpers (Blackwell FFMA2 — ptxas never auto-fuses from C++)
__device__ __forceinline__ u64 pk(float lo, float hi) {
    u64 r;
    asm("mov.b64 %0, {%1,%2};" : "=l"(r) : "f"(lo), "f"(hi));
    return r;
}
__device__ __forceinline__ void upk(u64 v, float& lo, float& hi) {
    asm("mov.b64 {%0,%1}, %2;" : "=f"(lo), "=f"(hi) : "l"(v));
}
__device__ __forceinline__ u64 fma2(u64 a, u64 b, u64 c) {
    u64 d;
    asm("fma.rn.f32x2 %0, %1, %2, %3;" : "=l"(d) : "l"(a), "l"(b), "l"(c));
    return d;
}
__device__ __forceinline__ u64 mul2(u64 a, u64 b) {
    u64 d;
    asm("mul.rn.f32x2 %0, %1, %2;" : "=l"(d) : "l"(a), "l"(b));
    return d;
}

// cp.async 16B: completion via commit-group counters
__device__ __forceinline__ void cp16(u32 smem_dst, const void* gsrc) {
    asm volatile("cp.async.cg.shared.global [%0], [%1], 16;"
                 :: "r"(smem_dst), "l"(gsrc) : "memory");
}
__device__ __forceinline__ void cp_commit() {
    asm volatile("cp.async.commit_group;" ::: "memory");
}
template <int N>
__device__ __forceinline__ void cp_wait() {
    asm volatile("cp.async.wait_group %0;" :: "n"(N) : "memory");
}

__device__ __forceinline__ u32 smem_u32(const void* p) {
    u32 a;
    asm("{ .reg .u64 t; cvta.to.shared.u64 t, %1; cvt.u32.u64 %0, t; }"
        : "=r"(a) : "l"(p));
    return a;
}

// ---------------------------------------------------------------------------
// Kernel A: input projection + mask -> [t][b]-major packed tiles.
// z/r pre-activations stored PRE-HALVED; mask stored as 0.5*m.
// ---------------------------------------------------------------------------
__global__ void __launch_bounds__(256) prep_kernel(
    const float* __restrict__ x,       // [B][T][8]
    const float* __restrict__ kern,    // [8][9]
    const float* __restrict__ bias_i,  // [9]
    const float* __restrict__ bias_r)  // [9]
{
    const int b  = blockIdx.x * 256 + threadIdx.x;
    const int t0 = blockIdx.y * 8;

    float bs[9];
#pragma unroll
    for (int j = 0; j < 9; j++) bs[j] = __ldg(bias_i + j) + __ldg(bias_r + j);
    float wv[8][9];
#pragma unroll
    for (int f = 0; f < 8; f++)
#pragma unroll
        for (int j = 0; j < 9; j++) wv[f][j] = __ldg(kern + f * 9 + j);

    const float4* x4 = reinterpret_cast<const float4*>(x) + (size_t)b * (Tt * 2);

#pragma unroll
    for (int i = 0; i < 8; i++) {
        const int t = t0 + i;
        float4 a = __ldg(x4 + (size_t)t * 2);
        float4 c = __ldg(x4 + (size_t)t * 2 + 1);
        float xf[8] = {a.x, a.y, a.z, a.w, c.x, c.y, c.z, c.w};

        float m = 0.0f;
#pragma unroll
        for (int f = 0; f < 8; f++)
            if (xf[f] != 0.0f) m = 0.5f;   // store 0.5*mask

        float acc[9];
#pragma unroll
        for (int j = 0; j < 9; j++) {
            float s = bs[j];
#pragma unroll
            for (int f = 0; f < 8; f++) s = fmaf(xf[f], wv[f][j], s);
            acc[j] = s;
        }

        const size_t o = (size_t)t * Bb + b;
        g_bufZ[o] = make_float4(0.5f * acc[0], 0.5f * acc[1], 0.5f * acc[2], m);
        g_bufR[o] = make_float4(0.5f * acc[3], 0.5f * acc[4], 0.5f * acc[5], 0.0f);
        g_bufH[o] = make_float4(acc[6], acc[7], acc[8], 0.0f);
    }
}

// ---------------------------------------------------------------------------
// One GRU row-step (math identical to R12). Updates h in place, returns out.
// ---------------------------------------------------------------------------
struct RkW {
    u64 Wp[3][4];
    float W8[3];
};

__device__ __forceinline__ float gru_step(
    float& h0, float& h1, float& h2,
    const float4 vz, const float4 vr, const float4 vh,
    const RkW& W, float w0, float w1, float w2, float db)
{
    const u64 h0x = pk(h0, h0);
    const u64 h1x = pk(h1, h1);
    const u64 h2x = pk(h2, h2);

    u64 a01  = fma2(h2x, W.Wp[2][0], fma2(h1x, W.Wp[1][0], fma2(h0x, W.Wp[0][0], pk(vz.x, vz.y))));
    u64 a2r0 = fma2(h2x, W.Wp[2][1], fma2(h1x, W.Wp[1][1], fma2(h0x, W.Wp[0][1], pk(vz.z, vr.x))));
    u64 a45  = fma2(h2x, W.Wp[2][2], fma2(h1x, W.Wp[1][2], fma2(h0x, W.Wp[0][2], pk(vr.y, vr.z))));
    u64 hh01 = fma2(h2x, W.Wp[2][3], fma2(h1x, W.Wp[1][3], mul2(h0x, W.Wp[0][3])));
    float hh2 = fmaf(h2, W.W8[2], fmaf(h1, W.W8[1], h0 * W.W8[0]));

    float az0, az1, az2, ar0, ar1, ar2, hh0, hh1;
    upk(a01, az0, az1);
    upk(a2r0, az2, ar0);
    upk(a45, ar1, ar2);
    upk(hh01, hh0, hh1);

    const float tz0 = tanh_fast(az0);
    const float tz1 = tanh_fast(az1);
    const float tz2 = tanh_fast(az2);
    const float tr0 = tanh_fast(ar0);
    const float tr1 = tanh_fast(ar1);
    const float tr2 = tanh_fast(ar2);

    const float halfm = vz.w;  // 0.5*mask

    const float g0 = fmaf(-halfm, tz0, halfm);
    const float g1 = fmaf(-halfm, tz1, halfm);
    const float g2 = fmaf(-halfm, tz2, halfm);

    const float r0 = fmaf(tr0, 0.5f, 0.5f);
    const float r1 = fmaf(tr1, 0.5f, 0.5f);
    const float r2 = fmaf(tr2, 0.5f, 0.5f);

    const float hc0 = tanh_fast(fmaf(r0, hh0, vh.x));
    const float hc1 = tanh_fast(fmaf(r1, hh1, vh.y));
    const float hc2 = tanh_fast(fmaf(r2, hh2, vh.z));

    h0 = fmaf(g0, hc0 - h0, h0);
    h1 = fmaf(g1, hc1 - h1, h1);
    h2 = fmaf(g2, hc2 - h2, h2);

    const float dot = fmaf(h2, w2, fmaf(h1, w1, h0 * w0));
    return fmaf(halfm, dot, db);
}

// ---------------------------------------------------------------------------
// Kernel B: sequential GRU scan, 32 blocks x 32 threads; each thread carries
// TWO independent batch rows (b, b+1024) -> two interleaved dependency
// chains per thread fill each other's stall slots. cp.async SMEM ring,
// 4 chunks x 4 steps, one wait+commit per chunk (R12 discipline).
// ---------------------------------------------------------------------------
__global__ void __launch_bounds__(32) scan_kernel(
    const float* __restrict__ rk,       // [3][9]
    const float* __restrict__ dense_w,  // [3][1]
    const float* __restrict__ dense_b)  // [1]
{
    __shared__ float4 ring[S][6][32];   // 48 KB: bufs 0-2 row A, 3-5 row B

    const int tid = threadIdx.x;
    const int bA = blockIdx.x * 32 + tid;
    const int bB = bA + 1024;

    // z/r columns (0..5) pre-halved to match pre-halved xz/xr.
    float rkv[3][9];
#pragma unroll
    for (int u = 0; u < 3; u++)
#pragma unroll
        for (int j = 0; j < 9; j++) {
            float v = __ldg(rk + u * 9 + j);
            rkv[u][j] = (j < 6) ? 0.5f * v : v;
        }

    RkW W;
#pragma unroll
    for (int u = 0; u < 3; u++) {
#pragma unroll
        for (int p = 0; p < 4; p++)
            W.Wp[u][p] = pk(rkv[u][2 * p], rkv[u][2 * p + 1]);
        W.W8[u] = rkv[u][8];
    }

    const float w0 = 2.0f * __ldg(dense_w);
    const float w1 = 2.0f * __ldg(dense_w + 1);
    const float w2 = 2.0f * __ldg(dense_w + 2);
    const float db = __ldg(dense_b);

    float hA0 = 0.0f, hA1 = 0.0f, hA2 = 0.0f;
    float hB0 = 0.0f, hB1 = 0.0f, hB2 = 0.0f;

    const u32 base = smem_u32(ring) + (tid << 4);
    // addr(stage st, buf q) = base + ((st*6 + q) << 9)

    // prologue: 4 chunk-groups (steps 0..15), one commit per chunk
#pragma unroll
    for (int c = 0; c < S / C; c++) {
#pragma unroll
        for (int s = 0; s < C; s++) {
            const int st = c * C + s;
            const size_t oA = (size_t)st * Bb + bA;
            const size_t oB = (size_t)st * Bb + bB;
            const u32 a = base + ((u32)(st * 6) << 9);
            cp16(a,            &g_bufZ[oA]);
            cp16(a + (1u << 9), &g_bufR[oA]);
            cp16(a + (2u << 9), &g_bufH[oA]);
            cp16(a + (3u << 9), &g_bufZ[oB]);
            cp16(a + (4u << 9), &g_bufR[oB]);
            cp16(a + (5u << 9), &g_bufH[oB]);
        }
        cp_commit();
    }

    // chunk 0 resident: committed=4, need group0 -> pending<=3
    cp_wait<3>();
    char* const rbase = (char*)ring + (tid << 4);
    float4 nzA = *reinterpret_cast<float4*>(rbase + (0 << 9));
    float4 nrA = *reinterpret_cast<float4*>(rbase + (1 << 9));
    float4 nhA = *reinterpret_cast<float4*>(rbase + (2 << 9));
    float4 nzB = *reinterpret_cast<float4*>(rbase + (3 << 9));
    float4 nrB = *reinterpret_cast<float4*>(rbase + (4 << 9));
    float4 nhB = *reinterpret_cast<float4*>(rbase + (5 << 9));

    for (int c = 0; c < Tt / C; c++) {
        const int base_t = c * C;
#pragma unroll
        for (int s = 0; s < C; s++) {
            const int tc = base_t + s;
            const int ns = (tc + 1) & (S - 1);   // next stage

            const float4 vzA = nzA, vrA = nrA, vhA = nhA;
            const float4 vzB = nzB, vrB = nrB, vhB = nhB;

            // Chunk boundary: ensure chunk c+1 resident.
            // committed = 4+c groups, need group c+1 done -> pending <= 2.
            if (s == C - 1) cp_wait<2>();

            {
                char* const p = rbase + (size_t)(ns * 6) * 512;
                nzA = *reinterpret_cast<float4*>(p + (0 << 9));
                nrA = *reinterpret_cast<float4*>(p + (1 << 9));
                nhA = *reinterpret_cast<float4*>(p + (2 << 9));
                nzB = *reinterpret_cast<float4*>(p + (3 << 9));
                nrB = *reinterpret_cast<float4*>(p + (4 << 9));
                nhB = *reinterpret_cast<float4*>(p + (5 << 9));
            }

            // Refill this chunk's slot with chunk c+4 (padded tail covers it).
            if (s == C - 1) {
                const int slot = c & 3;
#pragma unroll
                for (int q = 0; q < C; q++) {
                    const int st = slot * C + q;
                    const size_t oA = (size_t)(base_t + S + q) * Bb + bA;
                    const size_t oB = (size_t)(base_t + S + q) * Bb + bB;
                    const u32 a = base + ((u32)(st * 6) << 9);
                    cp16(a,             &g_bufZ[oA]);
                    cp16(a + (1u << 9), &g_bufR[oA]);
                    cp16(a + (2u << 9), &g_bufH[oA]);
                    cp16(a + (3u << 9), &g_bufZ[oB]);
                    cp16(a + (4u << 9), &g_bufR[oB]);
                    cp16(a + (5u << 9), &g_bufH[oB]);
                }
                cp_commit();
            }

            // Two independent GRU chains — compiler interleaves them,
            // each fills the other's latency stalls.
            const float outA = gru_step(hA0, hA1, hA2, vzA, vrA, vhA, W, w0, w1, w2, db);
            const float outB = gru_step(hB0, hB1, hB2, vzB, vrB, vhB, W, w0, w1, w2, db);

            g_outT[(size_t)tc * Bb + bA] = outA;
            g_outT[(size_t)tc * Bb + bB] = outB;
        }
    }
}

// ---------------------------------------------------------------------------
// Kernel C: transpose g_outT[t][b] -> out[b][t]
// ---------------------------------------------------------------------------
__global__ void transpose_kernel(float* __restrict__ out) {
    __shared__ float tile[32][33];
    const int bBase = blockIdx.x * 32;
    const int tBase = blockIdx.y * 32;

    tile[threadIdx.y][threadIdx.x] =
        g_outT[(size_t)(tBase + threadIdx.y) * Bb + (bBase + threadIdx.x)];
    __syncthreads();
    out[(size_t)(bBase + threadIdx.y) * Tt + (tBase + threadIdx.x)] =
        tile[threadIdx.x][threadIdx.y];
}

// ---------------------------------------------------------------------------
extern "C" void kernel_launch(void* const* d_in, const int* in_sizes, int n_in,
                              void* d_out, int out_size) {
    const float* x       = (const float*)d_in[0];  // (B,T,8)
    const float* kern    = (const float*)d_in[1];  // (8,9)
    const float* rk      = (const float*)d_in[2];  // (3,9)
    const float* bias_i  = (const float*)d_in[3];  // (9,)
    const float* bias_r  = (const float*)d_in[4];  // (9,)
    const float* dense_w = (const float*)d_in[5];  // (3,1)
    const float* dense_b = (const float*)d_in[6];  // (1,)
    float* out = (float*)d_out;                    // (B,T,1)

    (void)in_sizes; (void)n_in; (void)out_size;

    dim3 gA(Bb / 256, Tt / 8);
    prep_kernel<<<gA, 256>>>(x, kern, bias_i, bias_r);

    scan_kernel<<<NBLK, 32>>>(rk, dense_w, dense_b);

    dim3 gC(Bb / 32, Tt / 32);
    transpose_kernel<<<gC, dim3(32, 32)>>>(out);
}